// round 12
// baseline (speedup 1.0000x reference)
#include <cuda_runtime.h>
#include <cuda_fp16.h>
#include <cstdint>
#include <math.h>

#define FILTER_LEN 1024
#define HOP        512
#define CUTOFF     513
#define BATCH      8
#define TLEN       1048576
#define NFRAMES    2049
#define NGEMM      2048                    // frames in GEMM (n=2048 -> remainder)
#define KH         512                     // halved K via DFT symmetry

#define BMF     64                         // CTA freq tile
#define BN      128                        // CTA frame tile
#define KC      64                         // fp16 k per chunk (128 B rows)
#define NK      (KH / KC)                  // 8

// stage: AE(64x128B)+AO(64x128B)+BE(128x128B)+BO(128x128B); 2 stages
#define SAE     0
#define SAO     8192
#define SBE     16384
#define SBO     32768
#define STAGE   49152
#define DSMEM   (2 * STAGE)                // 96 KB -> 2 CTAs/SM

#define EXW     132                        // epilogue exchange row stride (floats)
#define NREM    (BATCH * (NFRAMES + 512))  // f=512 row + n=2048 col

// ---------------- device scratch -------------------------------------------
__device__ __align__(128) __half g_E [(size_t)BATCH * NGEMM * KH];
__device__ __align__(128) __half g_O [(size_t)BATCH * NGEMM * KH];
__device__ __align__(128) __half g_AE[(size_t)KH * KH];
__device__ __align__(128) __half g_AO[(size_t)KH * KH];

// ---------------- helpers ---------------------------------------------------
__device__ __forceinline__ uint32_t smem_u32(const void* p) {
    uint32_t a;
    asm("{ .reg .u64 t; cvta.to.shared.u64 t, %1; cvt.u32.u64 %0, t; }"
        : "=r"(a) : "l"(p));
    return a;
}
__device__ __forceinline__ void cp_async16(uint32_t dst, const void* src) {
    asm volatile("cp.async.cg.shared.global [%0], [%1], 16;"
                 :: "r"(dst), "l"(src) : "memory");
}
__device__ __forceinline__ void cp_commit() {
    asm volatile("cp.async.commit_group;" ::: "memory");
}
template <int N> __device__ __forceinline__ void cp_wait() {
    asm volatile("cp.async.wait_group %0;" :: "n"(N) : "memory");
}
__device__ __forceinline__ void ldsm_x4(uint32_t& r0, uint32_t& r1,
                                        uint32_t& r2, uint32_t& r3, uint32_t addr) {
    asm volatile("ldmatrix.sync.aligned.m8n8.x4.shared.b16 {%0,%1,%2,%3}, [%4];"
                 : "=r"(r0), "=r"(r1), "=r"(r2), "=r"(r3) : "r"(addr));
}
__device__ __forceinline__ void mma_f16(float* d, const uint32_t* a,
                                        uint32_t b0, uint32_t b1) {
    asm volatile(
        "mma.sync.aligned.m16n8k16.row.col.f32.f16.f16.f32 "
        "{%0,%1,%2,%3}, {%4,%5,%6,%7}, {%8,%9}, {%0,%1,%2,%3};"
        : "+f"(d[0]), "+f"(d[1]), "+f"(d[2]), "+f"(d[3])
        : "r"(a[0]), "r"(a[1]), "r"(a[2]), "r"(a[3]), "r"(b0), "r"(b1));
}
__device__ __forceinline__ uint32_t packh2(float a, float b) {
    __half2 t = __floats2half2_rn(a, b);
    return *reinterpret_cast<uint32_t*>(&t);
}
__device__ __forceinline__ int reflect_idx(int j) {
    if (j < 0) j = -j;
    else if (j >= TLEN) j = 2 * TLEN - 2 - j;
    return j;
}

// ---------------- prep 1: E/O via per-frame smem tile -----------------------
// block = one frame: load 1025-sample window coalesced, fold in smem
__global__ __launch_bounds__(128)
void eo_kernel(const float* __restrict__ x) {
    __shared__ float sx[1025];
    const int n = blockIdx.x;
    const int b = blockIdx.y;
    const int tid = threadIdx.x;
    const float* xb = x + (size_t)b * TLEN;
    const int base = n * HOP - 512;
    for (int t = tid; t < 1025; t += 128)
        sx[t] = xb[reflect_idx(base + t)];
    __syncthreads();

    const int j0 = tid * 4;
    float e[4], o[4];
    #pragma unroll
    for (int t = 0; t < 4; ++t) {
        const int j = j0 + t;
        const float x1 = sx[j];
        const float x2 = sx[1024 - j];
        e[t] = x1 + x2;
        o[t] = x1 - x2;
    }
    if (j0 == 0) { e[0] = sx[512]; o[0] = 0.f; }   // j=0 slots
    const size_t gbase = ((size_t)b * NGEMM + n) * KH + j0;
    *reinterpret_cast<uint2*>(g_E + gbase) = make_uint2(packh2(e[0], e[1]), packh2(e[2], e[3]));
    *reinterpret_cast<uint2*>(g_O + gbase) = make_uint2(packh2(o[0], o[1]), packh2(o[2], o[3]));
}

// ---------------- prep 2: symmetric/antisymmetric basis halves --------------
__global__ void basis_eo_kernel(const float* __restrict__ basis) {
    size_t v = (size_t)blockIdx.x * blockDim.x + threadIdx.x;   // 8-j group
    if (v >= (size_t)KH * (KH / 8)) return;
    const int jg = (int)(v % (KH / 8));
    const int f  = (int)(v / (KH / 8));
    const int j0 = jg * 8;
    const float* bR = basis + (size_t)f * FILTER_LEN;
    const float* bI = basis + (size_t)(CUTOFF + f) * FILTER_LEN;
    float ae[8], ao[8];
    #pragma unroll
    for (int t = 0; t < 8; ++t) {
        const int j = j0 + t;
        if (j == 0) {
            ae[t] = bR[512];
            ao[t] = 0.f;
        } else {
            ae[t] = 0.5f * (bR[j] + bR[FILTER_LEN - j]);
            ao[t] = 0.5f * (bI[j] - bI[FILTER_LEN - j]);
        }
    }
    const size_t base = (size_t)f * KH + j0;
    *reinterpret_cast<uint4*>(g_AE + base) =
        make_uint4(packh2(ae[0], ae[1]), packh2(ae[2], ae[3]),
                   packh2(ae[4], ae[5]), packh2(ae[6], ae[7]));
    *reinterpret_cast<uint4*>(g_AO + base) =
        make_uint4(packh2(ao[0], ao[1]), packh2(ao[2], ao[3]),
                   packh2(ao[4], ao[5]), packh2(ao[6], ao[7]));
}

// ---------------- main: R/I warp-specialized GEMM + fused magnitude ---------
__global__ __launch_bounds__(256, 2)
void stft_mma_kernel(const float* __restrict__ x,
                     const float* __restrict__ basis,
                     const float* __restrict__ eps_p,
                     float* __restrict__ out)
{
    const int tid  = threadIdx.x;
    const int wid  = tid >> 5;
    const int lane = tid & 31;

    // ======== remainder: f=512 row + n=2048 column, exact fp32 =============
    if (blockIdx.y == 8) {
        const float eps = *eps_p;
        const int stride = (int)(gridDim.x * gridDim.z) * 8;
        const int wbase = (int)(blockIdx.z * gridDim.x + blockIdx.x) * 8 + wid;
        for (int o = wbase; o < NREM; o += stride) {
            const int b = o / (NFRAMES + 512);
            const int r = o % (NFRAMES + 512);
            int f, n;
            if (r < NFRAMES) { f = 512; n = r; }
            else             { f = r - NFRAMES; n = 2048; }
            const float* bR = basis + (size_t)f * FILTER_LEN;
            const float* bI = basis + (size_t)(f + CUTOFF) * FILTER_LEN;
            const float* xb = x + (size_t)b * TLEN;
            float aR = 0.f, aI = 0.f;
            #pragma unroll 4
            for (int k = lane; k < FILTER_LEN; k += 32) {
                const int j = reflect_idx(n * HOP + k - 512);
                const float xv = xb[j];
                aR = fmaf(bR[k], xv, aR);
                aI = fmaf(bI[k], xv, aI);
            }
            #pragma unroll
            for (int s = 16; s; s >>= 1) {
                aR += __shfl_xor_sync(0xffffffffu, aR, s);
                aI += __shfl_xor_sync(0xffffffffu, aI, s);
            }
            if (lane == 0)
                out[((size_t)b * CUTOFF + f) * NFRAMES + n] =
                    sqrtf(fmaf(aR, aR, fmaf(aI, aI, eps)));
        }
        return;
    }

    // ======== dense GEMM: 64f x 128n CTA; warps 0-3 real, 4-7 imag =========
    extern __shared__ char dsm[];
    const uint32_t sbase = smem_u32(dsm);

    const int b  = blockIdx.z;
    const int m0 = blockIdx.y * BMF;
    const int n0 = blockIdx.x * BN;

    const int half = wid >> 2;             // 0 = real (AE*E), 1 = imag (AO*O)
    const int wg   = wid & 3;
    const int warp_f = (wg & 1) * 32;      // 0,32
    const int warp_n = (wg >> 1) * 64;     // 0,64
    const uint32_t AOFF = half ? SAO : SAE;
    const uint32_t BOFF = half ? SBO : SBE;

    // loader: AE/AO 512 chunks (2 rounds), BE/BO 1024 chunks (4 rounds)
    int a_row[2], a_c16[2]; uint32_t a_soff[2];
    #pragma unroll
    for (int j = 0; j < 2; ++j) {
        int chunk = tid + j * 256;
        a_row[j] = chunk >> 3;
        a_c16[j] = chunk & 7;
        a_soff[j] = (uint32_t)a_row[j] * 128 + (uint32_t)((a_c16[j] ^ (a_row[j] & 7)) * 16);
    }
    int b_row[4], b_c16[4]; uint32_t b_soff[4];
    #pragma unroll
    for (int j = 0; j < 4; ++j) {
        int chunk = tid + j * 256;
        b_row[j] = chunk >> 3;
        b_c16[j] = chunk & 7;
        b_soff[j] = (uint32_t)b_row[j] * 128 + (uint32_t)((b_c16[j] ^ (b_row[j] & 7)) * 16);
    }

    const __half* aE = g_AE + (size_t)m0 * KH;
    const __half* aO = g_AO + (size_t)m0 * KH;
    const __half* bE = g_E + ((size_t)b * NGEMM + n0) * KH;
    const __half* bO = g_O + ((size_t)b * NGEMM + n0) * KH;

    float acc[2][8][4];
    #pragma unroll
    for (int mt = 0; mt < 2; ++mt)
        #pragma unroll
        for (int nt = 0; nt < 8; ++nt)
            #pragma unroll
            for (int r = 0; r < 4; ++r) acc[mt][nt][r] = 0.f;

    const int lm_r = lane & 15;
    const int lm_s = lane >> 4;

    auto load_stage = [&](int i) {
        const uint32_t st = sbase + (uint32_t)(i & 1) * STAGE;
        const int k0 = i * KC;
        #pragma unroll
        for (int j = 0; j < 2; ++j) {
            const size_t off = (size_t)a_row[j] * KH + k0 + a_c16[j] * 8;
            cp_async16(st + SAE + a_soff[j], aE + off);
            cp_async16(st + SAO + a_soff[j], aO + off);
        }
        #pragma unroll
        for (int j = 0; j < 4; ++j) {
            const size_t off = (size_t)b_row[j] * KH + k0 + b_c16[j] * 8;
            cp_async16(st + SBE + b_soff[j], bE + off);
            cp_async16(st + SBO + b_soff[j], bO + off);
        }
        cp_commit();
    };

    load_stage(0);

    for (int i = 0; i < NK; ++i) {
        if (i + 1 < NK) { load_stage(i + 1); cp_wait<1>(); }
        else            { cp_wait<0>(); }
        __syncthreads();

        const uint32_t st = sbase + (uint32_t)(i & 1) * STAGE;

        #pragma unroll
        for (int ks = 0; ks < 4; ++ks) {
            const int c16 = ks * 2 + lm_s;
            uint32_t aF[2][4];
            #pragma unroll
            for (int mt = 0; mt < 2; ++mt) {
                const int row = warp_f + mt * 16 + lm_r;
                const uint32_t sw = (uint32_t)((c16 ^ (row & 7)) * 16);
                ldsm_x4(aF[mt][0], aF[mt][1], aF[mt][2], aF[mt][3],
                        st + AOFF + (uint32_t)row * 128 + sw);
            }
            #pragma unroll
            for (int g = 0; g < 4; ++g) {
                const int row = warp_n + g * 16 + lm_r;
                const uint32_t sw = (uint32_t)((c16 ^ (row & 7)) * 16);
                uint32_t bf[4];
                ldsm_x4(bf[0], bf[1], bf[2], bf[3],
                        st + BOFF + (uint32_t)row * 128 + sw);
                #pragma unroll
                for (int sub = 0; sub < 2; ++sub) {
                    const int nt = g * 2 + sub;
                    const uint32_t b0 = sub ? bf[1] : bf[0];
                    const uint32_t b1 = sub ? bf[3] : bf[2];
                    #pragma unroll
                    for (int mt = 0; mt < 2; ++mt)
                        mma_f16(acc[mt][nt], aF[mt], b0, b1);
                }
            }
        }
        __syncthreads();
    }

    // ---- epilogue: I warps dump to smem, R warps combine + store ----------
    float* ex = reinterpret_cast<float*>(dsm);     // 64 x EXW fp32 (34 KB)
    const float eps = *eps_p;
    const int r4 = lane >> 2;
    const int c2 = (lane & 3) * 2;

    if (half == 1) {
        #pragma unroll
        for (int mt = 0; mt < 2; ++mt) {
            #pragma unroll
            for (int nt = 0; nt < 8; ++nt) {
                const int fl = warp_f + mt * 16 + r4;
                const int nl = warp_n + nt * 8 + c2;
                #pragma unroll
                for (int cc = 0; cc < 2; ++cc) {
                    ex[fl * EXW + nl + cc]       = acc[mt][nt][cc];
                    ex[(fl + 8) * EXW + nl + cc] = acc[mt][nt][2 + cc];
                }
            }
        }
    }
    __syncthreads();
    if (half == 0) {
        #pragma unroll
        for (int mt = 0; mt < 2; ++mt) {
            #pragma unroll
            for (int nt = 0; nt < 8; ++nt) {
                const int fl = warp_f + mt * 16 + r4;
                const int nl = warp_n + nt * 8 + c2;
                #pragma unroll
                for (int cc = 0; cc < 2; ++cc) {
                    const float i0 = ex[fl * EXW + nl + cc];
                    const float i1 = ex[(fl + 8) * EXW + nl + cc];
                    const float r0 = acc[mt][nt][cc];
                    const float r1 = acc[mt][nt][2 + cc];
                    const int n = n0 + nl + cc;
                    out[((size_t)b * CUTOFF + m0 + fl) * NFRAMES + n] =
                        sqrtf(fmaf(r0, r0, fmaf(i0, i0, eps)));
                    out[((size_t)b * CUTOFF + m0 + fl + 8) * NFRAMES + n] =
                        sqrtf(fmaf(r1, r1, fmaf(i1, i1, eps)));
                }
            }
        }
    }
}

// ---------------- launch ----------------------------------------------------
extern "C" void kernel_launch(void* const* d_in, const int* in_sizes, int n_in,
                              void* d_out, int out_size)
{
    const float* x     = (const float*)d_in[0];
    const float* basis = (const float*)d_in[1];
    const float* eps   = (const float*)d_in[2];
    float* out = (float*)d_out;

    {
        dim3 grid(NGEMM, BATCH);
        eo_kernel<<<grid, 128>>>(x);
    }
    {
        size_t tot = (size_t)KH * (KH / 8);
        basis_eo_kernel<<<(unsigned)((tot + 255) / 256), 256>>>(basis);
    }
    {
        cudaFuncSetAttribute(stft_mma_kernel,
                             cudaFuncAttributeMaxDynamicSharedMemorySize, DSMEM);
        dim3 grid(16, 9, BATCH);     // y<8: GEMM; y==8: fp32 remainder
        stft_mma_kernel<<<grid, 256, DSMEM>>>(x, basis, eps, out);
    }
}